// round 6
// baseline (speedup 1.0000x reference)
#include <cuda_runtime.h>

#define N_NODES 50000
#define N_EDGES 800000
#define DIM 64
#define NLAYERS 3
#define LN_EPS 1e-5f

// ---------------- device scratch (no allocations allowed) ----------------
__device__ float g_bufA[(size_t)N_NODES * DIM];
__device__ float g_bufB[(size_t)N_NODES * DIM];
__device__ int   g_deg[N_NODES];
__device__ int   g_rowptr[N_NODES + 1];
__device__ int   g_cursor[N_NODES];
__device__ int   g_colidx[N_EDGES];
__device__ float g_wv[N_EDGES];      // per-edge norm weight dinv[src]*dinv[dst]
__device__ float g_dinv[N_NODES];

// ---------------- CSR construction ----------------
__global__ void zero_deg_kernel() {
    int i = blockIdx.x * blockDim.x + threadIdx.x;
    if (i < N_NODES) g_deg[i] = 0;
}

__global__ void hist_kernel(const int* __restrict__ dst) {
    int e = blockIdx.x * blockDim.x + threadIdx.x;
    if (e < N_EDGES) atomicAdd(&g_deg[__ldg(dst + e)], 1);
}

// Single-block exclusive scan over 50k degrees + dinv computation.
__global__ void scan_kernel() {
    __shared__ int ssum[1024];
    const int CH = (N_NODES + 1023) / 1024;  // 49
    int t = threadIdx.x;
    int base = t * CH;
    int sum = 0;
    for (int i = 0; i < CH; i++) {
        int idx = base + i;
        if (idx < N_NODES) sum += g_deg[idx];
    }
    ssum[t] = sum;
    __syncthreads();
    for (int off = 1; off < 1024; off <<= 1) {
        int v = (t >= off) ? ssum[t - off] : 0;
        __syncthreads();
        ssum[t] += v;
        __syncthreads();
    }
    int run = ssum[t] - sum;  // exclusive prefix of this chunk
    for (int i = 0; i < CH; i++) {
        int idx = base + i;
        if (idx < N_NODES) {
            int d = g_deg[idx];
            g_rowptr[idx] = run;
            g_cursor[idx] = run;
            g_dinv[idx]   = rsqrtf((float)(d + 1));  // +1 self-loop
            run += d;
        }
    }
    if (t == 0) g_rowptr[N_NODES] = N_EDGES;
}

__global__ void fill_csr_kernel(const int* __restrict__ src,
                                const int* __restrict__ dst) {
    int e = blockIdx.x * blockDim.x + threadIdx.x;
    if (e < N_EDGES) {
        int s = __ldg(src + e);
        int d = __ldg(dst + e);
        int pos = atomicAdd(&g_cursor[d], 1);
        g_colidx[pos] = s;
        g_wv[pos]     = __ldg(g_dinv + s) * __ldg(g_dinv + d);
    }
}

// ---------------- fused layer: aggregate(X) -> @W -> +bias -> LN -> ReLU ----
// One warp per node; lane owns cols [2*lane, 2*lane+1].
// Uses the identity A_norm (X W) == (A_norm X) W.
#define NPW 4           // nodes per warp
#define LTHREADS 512    // 16 warps per block
__global__ void __launch_bounds__(LTHREADS)
layer_kernel(const float* __restrict__ Pin,
             const float* __restrict__ W,
             const float* __restrict__ bias,
             const float* __restrict__ gamma,
             const float* __restrict__ beta,
             float* __restrict__ Qout) {
    __shared__ float sW[DIM * DIM];
    int tid = threadIdx.x;
    for (int idx = tid; idx < DIM * DIM; idx += LTHREADS) sW[idx] = W[idx];
    __syncthreads();

    int lane = tid & 31;
    int warp = tid >> 5;
    const float2* __restrict__ P2 = (const float2*)Pin;
    const float2* sW2 = (const float2*)sW;

    // per-lane layer constants
    float b0  = bias[2 * lane],  b1  = bias[2 * lane + 1];
    float ga0 = gamma[2 * lane], ga1 = gamma[2 * lane + 1];
    float be0 = beta[2 * lane],  be1 = beta[2 * lane + 1];

    int nodeBase = (blockIdx.x * (LTHREADS / 32) + warp) * NPW;

    #pragma unroll
    for (int r = 0; r < NPW; r++) {
        int node = nodeBase + r;
        if (node >= N_NODES) return;

        // ---- normalized aggregation of previous activations ----
        float di = g_dinv[node];
        float2 xs = __ldg(P2 + (size_t)node * (DIM / 2) + lane);
        float sl = di * di;
        float accx = sl * xs.x;
        float accy = sl * xs.y;

        int s0 = g_rowptr[node];
        int s1 = g_rowptr[node + 1];
        for (int b = s0; b < s1; b += 32) {
            int n = s1 - b;
            if (n > 32) n = 32;
            int   srcn = 0;
            float w    = 0.f;
            if (lane < n) {
                srcn = __ldg(g_colidx + b + lane);
                w    = __ldg(g_wv + b + lane);
            }
            // software pipeline: load edge k+1 before FMA of edge k
            int   sk = __shfl_sync(0xffffffffu, srcn, 0);
            float wk = __shfl_sync(0xffffffffu, w, 0);
            float2 v = __ldg(P2 + (size_t)sk * (DIM / 2) + lane);
            for (int k = 0; k < n; k++) {
                float2 vcur = v;
                float  wcur = wk;
                if (k + 1 < n) {
                    int sn = __shfl_sync(0xffffffffu, srcn, k + 1);
                    wk = __shfl_sync(0xffffffffu, w, k + 1);
                    v  = __ldg(P2 + (size_t)sn * (DIM / 2) + lane);
                }
                accx = fmaf(wcur, vcur.x, accx);
                accy = fmaf(wcur, vcur.y, accy);
            }
        }

        // ---- in-warp 1x64 @ 64x64 transform (W in smem) ----
        float ox = 0.f, oy = 0.f;
        #pragma unroll
        for (int k = 0; k < DIM; k++) {
            float ak = __shfl_sync(0xffffffffu, (k & 1) ? accy : accx, k >> 1);
            float2 w2 = sW2[k * 32 + lane];
            ox = fmaf(ak, w2.x, ox);
            oy = fmaf(ak, w2.y, oy);
        }

        ox += b0;
        oy += b1;

        // ---- LayerNorm over 64 features (warp reduction) + ReLU ----
        float s  = ox + oy;
        float sq = ox * ox + oy * oy;
        #pragma unroll
        for (int o = 16; o; o >>= 1) {
            s  += __shfl_xor_sync(0xffffffffu, s,  o);
            sq += __shfl_xor_sync(0xffffffffu, sq, o);
        }
        float mu   = s * (1.0f / DIM);
        float var  = sq * (1.0f / DIM) - mu * mu;
        float rstd = rsqrtf(var + LN_EPS);
        float y0 = fmaxf((ox - mu) * rstd * ga0 + be0, 0.f);
        float y1 = fmaxf((oy - mu) * rstd * ga1 + be1, 0.f);
        ((float2*)(Qout + (size_t)node * DIM))[lane] = make_float2(y0, y1);
    }
}

// ---------------- launch ----------------
extern "C" void kernel_launch(void* const* d_in, const int* in_sizes, int n_in,
                              void* d_out, int out_size) {
    const float* x     = (const float*)d_in[0];
    const int*   ei    = (const int*)  d_in[1];   // [2, E] row-major
    const float* Ws    = (const float*)d_in[2];   // [3, 64, 64]
    const float* bs    = (const float*)d_in[3];   // [3, 64]
    const float* gs    = (const float*)d_in[4];   // [3, 64]
    const float* betas = (const float*)d_in[5];   // [3, 64]
    const int* srcp = ei;
    const int* dstp = ei + N_EDGES;
    float* out = (float*)d_out;

    zero_deg_kernel<<<(N_NODES + 255) / 256, 256>>>();
    hist_kernel<<<(N_EDGES + 255) / 256, 256>>>(dstp);
    scan_kernel<<<1, 1024>>>();
    fill_csr_kernel<<<(N_EDGES + 255) / 256, 256>>>(srcp, dstp);

    const int nodes_per_block = (LTHREADS / 32) * NPW;  // 64
    const int layer_blocks = (N_NODES + nodes_per_block - 1) / nodes_per_block;

    float* bufA; cudaGetSymbolAddress((void**)&bufA, g_bufA);
    float* bufB; cudaGetSymbolAddress((void**)&bufB, g_bufB);

    layer_kernel<<<layer_blocks, LTHREADS>>>(x,    Ws,                 bs,          gs,          betas,          bufA);
    layer_kernel<<<layer_blocks, LTHREADS>>>(bufA, Ws + DIM * DIM,     bs + DIM,    gs + DIM,    betas + DIM,    bufB);
    layer_kernel<<<layer_blocks, LTHREADS>>>(bufB, Ws + 2 * DIM * DIM, bs + 2*DIM,  gs + 2*DIM,  betas + 2*DIM,  out);
}